// round 12
// baseline (speedup 1.0000x reference)
#include <cuda_runtime.h>
#include <cuda_fp16.h>
#include <stdint.h>

// ---------------------------------------------------------------------------
// Pure fp16 GEMMs (fp32 accum) on mma.sync. R12 = R11 mainloop (CTA 128x128,
// 256 thr, 2 CTAs/SM, Kc=64, 3-stage cp.async, one barrier/chunk) +
// persistent-CTA tiling (kills wave-quantization tails) + hardware
// tanh.approx GELU epilogue (~2.5x cheaper than erff).
// ---------------------------------------------------------------------------

#define STAGE_BYTES 32768          // A[2][128][64B] 16K | B[2][128][64B] 16K
#define NSTAGES 3
#define SMEM_TOTAL (NSTAGES * STAGE_BYTES)   // 96 KB -> 2 CTAs/SM
#define NPERSIST 296               // 148 SMs x 2 CTAs

// ---------------- static device scratch (no allocations allowed) -----------
static __device__ __align__(16) __half g_Xh [(size_t)32768 * 768];
static __device__ __align__(16) __half g_W1t[(size_t)3072 * 768];     // [N][K]
static __device__ __align__(16) __half g_W2t[(size_t)576 * 3072];     // [N][K]
static __device__ __align__(16) __half g_Wet[(size_t)6 * 192 * 3072];
static __device__ __align__(16) __half g_Hf [(size_t)32768 * 3072];

// ---------------- PTX helpers ----------------------------------------------
__device__ __forceinline__ uint32_t smem_u32(const void* p) {
    uint32_t a;
    asm("{ .reg .u64 t; cvta.to.shared.u64 t, %1; cvt.u32.u64 %0, t; }" : "=r"(a) : "l"(p));
    return a;
}
__device__ __forceinline__ void cp16(uint32_t saddr, const void* g) {
    asm volatile("cp.async.cg.shared.global [%0], [%1], 16;" :: "r"(saddr), "l"(g));
}
#define CP_COMMIT() asm volatile("cp.async.commit_group;" ::: "memory")
#define CP_WAIT(n)  asm volatile("cp.async.wait_group " #n ";" ::: "memory")

__device__ __forceinline__ void ldsm4(uint32_t* r, uint32_t addr) {
    asm volatile("ldmatrix.sync.aligned.m8n8.x4.shared.b16 {%0,%1,%2,%3}, [%4];"
        : "=r"(r[0]), "=r"(r[1]), "=r"(r[2]), "=r"(r[3]) : "r"(addr));
}
__device__ __forceinline__ void mma_f16(float* c, const uint32_t* a,
                                        uint32_t b0, uint32_t b1) {
    asm volatile("mma.sync.aligned.m16n8k16.row.col.f32.f16.f16.f32 "
        "{%0,%1,%2,%3}, {%4,%5,%6,%7}, {%8,%9}, {%0,%1,%2,%3};"
        : "+f"(c[0]), "+f"(c[1]), "+f"(c[2]), "+f"(c[3])
        : "r"(a[0]), "r"(a[1]), "r"(a[2]), "r"(a[3]), "r"(b0), "r"(b1));
}

// gelu via hardware tanh.approx.f32 (single MUFU op):
// 0.5*x*(1 + tanh(0.7978845608*x*(1 + 0.044715*x^2)))
__device__ __forceinline__ float gelu_fast(float x) {
    float u = 0.7978845608028654f * x * fmaf(0.044715f * x, x, 1.0f);
    float t;
    asm("tanh.approx.f32 %0, %1;" : "=f"(t) : "f"(u));
    return 0.5f * x * (1.0f + t);
}
// int64-vs-int32 robust expert index (values in [0,6) -> int64 odd words all 0)
__device__ __forceinline__ int load_expert_index(const int* __restrict__ idx32, int b) {
    int odd_or = 0;
    #pragma unroll
    for (int j = 1; j < 32; j += 2) odd_or |= idx32[j];
    return (odd_or == 0) ? idx32[2 * b] : idx32[b];
}

// ---------------- prep kernels ----------------------------------------------
__global__ void k_half(const float* __restrict__ s, __half* __restrict__ d, size_t n)
{
    size_t i = ((size_t)blockIdx.x * blockDim.x + threadIdx.x) * 4;
    if (i >= n) return;
    float4 v = *(const float4*)(s + i);
    __half2 a = __floats2half2_rn(v.x, v.y);
    __half2 b = __floats2half2_rn(v.z, v.w);
    uint2 o;
    o.x = *reinterpret_cast<uint32_t*>(&a);
    o.y = *reinterpret_cast<uint32_t*>(&b);
    *(uint2*)(d + i) = o;
}

__global__ void k_thalf(const float* __restrict__ src, __half* __restrict__ dst,
                        int R, int C)
{
    __shared__ float t[32][33];
    size_t zo = (size_t)blockIdx.z * R * C;
    int bx = blockIdx.x * 32, by = blockIdx.y * 32;
    int tx = threadIdx.x, ty = threadIdx.y;  // (32, 8)
    #pragma unroll
    for (int i = 0; i < 32; i += 8)
        t[ty + i][tx] = src[zo + (size_t)(by + ty + i) * C + bx + tx];
    __syncthreads();
    #pragma unroll
    for (int i = 0; i < 32; i += 8) {
        size_t o = zo + (size_t)(bx + ty + i) * R + (by + tx);
        dst[o] = __float2half_rn(t[tx][ty + i]);
    }
}

// ---------------------------------------------------------------------------
// Mainloop compute: chunk = 64 K-columns as two 32-col sub-blocks.
// Stage: A sub0 +0, A sub1 +8192, B sub0 +16384, B sub1 +24576.
// Each sub-block: 128 rows x 64 B, 16B-chunk swizzle p = ch ^ ((r>>1)&3).
// ---------------------------------------------------------------------------

struct Frags {
    float acc[2][8][4];
};

__device__ __forceinline__ void compute_chunk(uint32_t base, int st, int lane,
                                              int wm, int wn, Frags& F)
{
    const uint32_t Ab = base + st;
    const uint32_t Bb = base + st + 16384;
    const int m8 = lane >> 3, l7 = lane & 7;
    #pragma unroll
    for (int ks = 0; ks < 4; ks++) {
        const uint32_t Asub = Ab + (ks >> 1) * 8192;
        const uint32_t Bsub = Bb + (ks >> 1) * 8192;
        const int kk = ks & 1;
        uint32_t a[2][4];
        #pragma unroll
        for (int mi = 0; mi < 2; mi++) {
            int rr = wm * 32 + mi * 16 + (m8 & 1) * 8 + l7;
            int ch = kk * 2 + (m8 >> 1);
            int p = ch ^ ((rr >> 1) & 3);
            ldsm4(a[mi], Asub + (uint32_t)(rr * 64 + p * 16));
        }
        #pragma unroll
        for (int jp = 0; jp < 4; jp++) {
            int nrow = wn * 64 + jp * 16 + (m8 >> 1) * 8 + l7;
            int ch = kk * 2 + (m8 & 1);
            int p = ch ^ ((nrow >> 1) & 3);
            uint32_t tb[4];
            ldsm4(tb, Bsub + (uint32_t)(nrow * 64 + p * 16));
            #pragma unroll
            for (int mi = 0; mi < 2; mi++) {
                mma_f16(F.acc[mi][2 * jp],     a[mi], tb[0], tb[1]);
                mma_f16(F.acc[mi][2 * jp + 1], a[mi], tb[2], tb[3]);
            }
        }
    }
}

// ---------------------------------------------------------------------------
// GEMM1 (persistent): H = gelu(X @ W1 + b1).  Tiles 24 x 256 (bx fastest),
// grid NPERSIST, 256 threads, 2 CTAs/SM.  NC = 768/64 = 12.
// ---------------------------------------------------------------------------
__global__ void __launch_bounds__(256, 2)
k_mm1(const float* __restrict__ b1)
{
    extern __shared__ char smem[];
    const uint32_t base = smem_u32(smem);
    const int tid = threadIdx.x, wid = tid >> 5, lane = tid & 31;
    const int K = 768, NC = 12, NTILES = 24 * 256;
    const int wm = wid & 3, wn = wid >> 2;
    const int g = lane >> 2, t4 = lane & 3;

    for (int tile = blockIdx.x; tile < NTILES; tile += NPERSIST) {
        const int bx = tile % 24, by = tile / 24;

        auto issue = [&](int c) {
            int st = (c % NSTAGES) * STAGE_BYTES;
            #pragma unroll
            for (int t = 0; t < 8; t++) {
                int idx = tid + t * 256;           // 0..2047
                int region = idx >> 9;             // 0: A0, 1: A1, 2: B0, 3: B1
                int w = idx & 511, r = w >> 2, ch = w & 3;
                int sub = region & 1;
                int isB = region >> 1;
                int p = ch ^ ((r >> 1) & 3);
                uint32_t sa = base + st + isB * 16384 + sub * 8192 + r * 64 + p * 16;
                const __half* src;
                size_t grow;
                if (!isB) { src = g_Xh;  grow = (size_t)(by * 128 + r) * K; }
                else      { src = g_W1t; grow = (size_t)(bx * 128 + r) * K; }
                cp16(sa, src + grow + c * 64 + sub * 32 + ch * 8);
            }
            CP_COMMIT();
        };

        Frags F;
        #pragma unroll
        for (int mi = 0; mi < 2; mi++)
            #pragma unroll
            for (int nj = 0; nj < 8; nj++)
                #pragma unroll
                for (int q = 0; q < 4; q++) F.acc[mi][nj][q] = 0.0f;

        issue(0); issue(1);
        for (int c = 0; c < NC; c++) {
            CP_WAIT(1);
            __syncthreads();
            if (c + 2 < NC) issue(c + 2); else CP_COMMIT();
            compute_chunk(base, (c % NSTAGES) * STAGE_BYTES, lane, wm, wn, F);
        }

        // epilogue: bias + fast GELU -> fp16 into H
        #pragma unroll
        for (int mi = 0; mi < 2; mi++) {
            #pragma unroll
            for (int nj = 0; nj < 8; nj++) {
                int row0 = by * 128 + wm * 32 + mi * 16 + g;
                int col  = bx * 128 + wn * 64 + nj * 8 + 2 * t4;
                float2 bb = *(const float2*)(b1 + col);
                float x0 = gelu_fast(F.acc[mi][nj][0] + bb.x);
                float x1 = gelu_fast(F.acc[mi][nj][1] + bb.y);
                float x2 = gelu_fast(F.acc[mi][nj][2] + bb.x);
                float x3 = gelu_fast(F.acc[mi][nj][3] + bb.y);
                __half2 h01 = __floats2half2_rn(x0, x1);
                __half2 h23 = __floats2half2_rn(x2, x3);
                *(uint32_t*)(g_Hf + (size_t)row0 * 3072 + col) =
                    *reinterpret_cast<uint32_t*>(&h01);
                *(uint32_t*)(g_Hf + (size_t)(row0 + 8) * 3072 + col) =
                    *reinterpret_cast<uint32_t*>(&h23);
            }
        }
    }
}

// ---------------------------------------------------------------------------
// GEMM2 (persistent): out = H @ [W2 | We[idx]] + [b2 | be[idx]].
// Tiles 6 x 256 (bx fastest), grid NPERSIST, 2 CTAs/SM. NC = 3072/64 = 48.
// B rows n<576 from W2t, n>=576 from Wet[e]; 128-row M tiles never straddle
// a batch (1024 rows / batch).
// ---------------------------------------------------------------------------
__global__ void __launch_bounds__(256, 2)
k_mm2(const float* __restrict__ b2, const float* __restrict__ be,
      const int* __restrict__ idx32, float* __restrict__ out)
{
    extern __shared__ char smem[];
    const uint32_t base = smem_u32(smem);
    const int tid = threadIdx.x, wid = tid >> 5, lane = tid & 31;
    const int K = 3072, NC = 48, NTILES = 6 * 256;
    const int wm = wid & 3, wn = wid >> 2;
    const int g = lane >> 2, t4 = lane & 3;

    for (int tile = blockIdx.x; tile < NTILES; tile += NPERSIST) {
        const int bx = tile % 6, by = tile / 6;
        const int e = load_expert_index(idx32, by >> 3);

        auto issue = [&](int c) {
            int st = (c % NSTAGES) * STAGE_BYTES;
            #pragma unroll
            for (int t = 0; t < 8; t++) {
                int idx = tid + t * 256;
                int region = idx >> 9;
                int w = idx & 511, r = w >> 2, ch = w & 3;
                int sub = region & 1;
                int isB = region >> 1;
                int p = ch ^ ((r >> 1) & 3);
                uint32_t sa = base + st + isB * 16384 + sub * 8192 + r * 64 + p * 16;
                const __half* src;
                size_t grow;
                if (!isB) {
                    src = g_Hf;
                    grow = (size_t)(by * 128 + r) * K;
                } else {
                    int n = bx * 128 + r;
                    if (n < 576) { src = g_W2t; grow = (size_t)n * K; }
                    else { src = g_Wet; grow = ((size_t)e * 192 + (n - 576)) * K; }
                }
                cp16(sa, src + grow + c * 64 + sub * 32 + ch * 8);
            }
            CP_COMMIT();
        };

        Frags F;
        #pragma unroll
        for (int mi = 0; mi < 2; mi++)
            #pragma unroll
            for (int nj = 0; nj < 8; nj++)
                #pragma unroll
                for (int q = 0; q < 4; q++) F.acc[mi][nj][q] = 0.0f;

        issue(0); issue(1);
        for (int c = 0; c < NC; c++) {
            CP_WAIT(1);
            __syncthreads();
            if (c + 2 < NC) issue(c + 2); else CP_COMMIT();
            compute_chunk(base, (c % NSTAGES) * STAGE_BYTES, lane, wm, wn, F);
        }

        // epilogue: + bias (shared / expert), fp32 out [32768][768]
        #pragma unroll
        for (int mi = 0; mi < 2; mi++) {
            #pragma unroll
            for (int nj = 0; nj < 8; nj++) {
                int row0 = by * 128 + wm * 32 + mi * 16 + g;
                int col  = bx * 128 + wn * 64 + nj * 8 + 2 * t4;
                float bx0, bx1;
                if (col < 576) { float2 bb = *(const float2*)(b2 + col); bx0 = bb.x; bx1 = bb.y; }
                else { float2 bb = *(const float2*)(be + e * 192 + (col - 576)); bx0 = bb.x; bx1 = bb.y; }
                float2 v0 = make_float2(F.acc[mi][nj][0] + bx0, F.acc[mi][nj][1] + bx1);
                float2 v1 = make_float2(F.acc[mi][nj][2] + bx0, F.acc[mi][nj][3] + bx1);
                *(float2*)(out + (size_t)row0 * 768 + col) = v0;
                *(float2*)(out + (size_t)(row0 + 8) * 768 + col) = v1;
            }
        }
    }
}

// ---------------------------------------------------------------------------
extern "C" void kernel_launch(void* const* d_in, const int* in_sizes, int n_in,
                              void* d_out, int out_size)
{
    (void)in_sizes; (void)n_in; (void)out_size;
    const float* X   = (const float*)d_in[0];
    const int*   idx = (const int*)d_in[1];
    const float* W1  = (const float*)d_in[2];
    const float* b1  = (const float*)d_in[3];
    const float* W2  = (const float*)d_in[4];
    const float* b2  = (const float*)d_in[5];
    const float* We  = (const float*)d_in[6];
    const float* be  = (const float*)d_in[7];
    float* out = (float*)d_out;

    cudaFuncSetAttribute(k_mm1, cudaFuncAttributeMaxDynamicSharedMemorySize, SMEM_TOTAL);
    cudaFuncSetAttribute(k_mm2, cudaFuncAttributeMaxDynamicSharedMemorySize, SMEM_TOTAL);

    __half *xh, *w1t, *w2t, *wet;
    cudaGetSymbolAddress((void**)&xh,  g_Xh);
    cudaGetSymbolAddress((void**)&w1t, g_W1t);
    cudaGetSymbolAddress((void**)&w2t, g_W2t);
    cudaGetSymbolAddress((void**)&wet, g_Wet);

    {
        size_t n = (size_t)32768 * 768;
        k_half<<<(unsigned)(n / (256 * 4)), 256>>>(X, xh, n);
    }
    {
        dim3 b(32, 8);
        k_thalf<<<dim3(3072 / 32, 768 / 32, 1), b>>>(W1, w1t, 768, 3072);
        k_thalf<<<dim3(576 / 32, 3072 / 32, 1), b>>>(W2, w2t, 3072, 576);
        k_thalf<<<dim3(192 / 32, 3072 / 32, 6), b>>>(We, wet, 3072, 192);
    }

    k_mm1<<<NPERSIST, 256, SMEM_TOTAL>>>(b1);
    k_mm2<<<NPERSIST, 256, SMEM_TOTAL>>>(b2, be, idx, out);
}

// round 13
// speedup vs baseline: 1.6137x; 1.6137x over previous
#include <cuda_runtime.h>
#include <cuda_fp16.h>
#include <stdint.h>

// ---------------------------------------------------------------------------
// Pure fp16 GEMMs (fp32 accum) on mma.sync. R13 = exact R11 structure
// (CTA 128x128, 256 thr, 2 CTAs/SM, Kc=64, 3-stage cp.async, one
// barrier/chunk, launched grid — persistence reverted, it broke co-residency)
// with only the hardware tanh.approx GELU kept from R12.
// ---------------------------------------------------------------------------

#define STAGE_BYTES 32768          // A[2][128][64B] 16K | B[2][128][64B] 16K
#define NSTAGES 3
#define SMEM_TOTAL (NSTAGES * STAGE_BYTES)   // 96 KB -> 2 CTAs/SM

// ---------------- static device scratch (no allocations allowed) -----------
static __device__ __align__(16) __half g_Xh [(size_t)32768 * 768];
static __device__ __align__(16) __half g_W1t[(size_t)3072 * 768];     // [N][K]
static __device__ __align__(16) __half g_W2t[(size_t)576 * 3072];     // [N][K]
static __device__ __align__(16) __half g_Wet[(size_t)6 * 192 * 3072];
static __device__ __align__(16) __half g_Hf [(size_t)32768 * 3072];

// ---------------- PTX helpers ----------------------------------------------
__device__ __forceinline__ uint32_t smem_u32(const void* p) {
    uint32_t a;
    asm("{ .reg .u64 t; cvta.to.shared.u64 t, %1; cvt.u32.u64 %0, t; }" : "=r"(a) : "l"(p));
    return a;
}
__device__ __forceinline__ void cp16(uint32_t saddr, const void* g) {
    asm volatile("cp.async.cg.shared.global [%0], [%1], 16;" :: "r"(saddr), "l"(g));
}
#define CP_COMMIT() asm volatile("cp.async.commit_group;" ::: "memory")
#define CP_WAIT(n)  asm volatile("cp.async.wait_group " #n ";" ::: "memory")

__device__ __forceinline__ void ldsm4(uint32_t* r, uint32_t addr) {
    asm volatile("ldmatrix.sync.aligned.m8n8.x4.shared.b16 {%0,%1,%2,%3}, [%4];"
        : "=r"(r[0]), "=r"(r[1]), "=r"(r[2]), "=r"(r[3]) : "r"(addr));
}
__device__ __forceinline__ void mma_f16(float* c, const uint32_t* a,
                                        uint32_t b0, uint32_t b1) {
    asm volatile("mma.sync.aligned.m16n8k16.row.col.f32.f16.f16.f32 "
        "{%0,%1,%2,%3}, {%4,%5,%6,%7}, {%8,%9}, {%0,%1,%2,%3};"
        : "+f"(c[0]), "+f"(c[1]), "+f"(c[2]), "+f"(c[3])
        : "r"(a[0]), "r"(a[1]), "r"(a[2]), "r"(a[3]), "r"(b0), "r"(b1));
}

// gelu via hardware tanh.approx.f32 (single MUFU op):
// 0.5*x*(1 + tanh(0.7978845608*x*(1 + 0.044715*x^2)))
__device__ __forceinline__ float gelu_fast(float x) {
    float u = 0.7978845608028654f * x * fmaf(0.044715f * x, x, 1.0f);
    float t;
    asm("tanh.approx.f32 %0, %1;" : "=f"(t) : "f"(u));
    return 0.5f * x * (1.0f + t);
}
// int64-vs-int32 robust expert index (values in [0,6) -> int64 odd words all 0)
__device__ __forceinline__ int load_expert_index(const int* __restrict__ idx32, int b) {
    int odd_or = 0;
    #pragma unroll
    for (int j = 1; j < 32; j += 2) odd_or |= idx32[j];
    return (odd_or == 0) ? idx32[2 * b] : idx32[b];
}

// ---------------- prep kernels ----------------------------------------------
// fp32 -> fp16 elementwise (vectorized x4)
__global__ void k_half(const float* __restrict__ s, __half* __restrict__ d, size_t n)
{
    size_t i = ((size_t)blockIdx.x * blockDim.x + threadIdx.x) * 4;
    if (i >= n) return;
    float4 v = *(const float4*)(s + i);
    __half2 a = __floats2half2_rn(v.x, v.y);
    __half2 b = __floats2half2_rn(v.z, v.w);
    uint2 o;
    o.x = *reinterpret_cast<uint32_t*>(&a);
    o.y = *reinterpret_cast<uint32_t*>(&b);
    *(uint2*)(d + i) = o;
}

// transpose [R][C] fp32 -> [C][R] fp16 (batched over z)
__global__ void k_thalf(const float* __restrict__ src, __half* __restrict__ dst,
                        int R, int C)
{
    __shared__ float t[32][33];
    size_t zo = (size_t)blockIdx.z * R * C;
    int bx = blockIdx.x * 32, by = blockIdx.y * 32;
    int tx = threadIdx.x, ty = threadIdx.y;  // (32, 8)
    #pragma unroll
    for (int i = 0; i < 32; i += 8)
        t[ty + i][tx] = src[zo + (size_t)(by + ty + i) * C + bx + tx];
    __syncthreads();
    #pragma unroll
    for (int i = 0; i < 32; i += 8) {
        size_t o = zo + (size_t)(bx + ty + i) * R + (by + tx);
        dst[o] = __float2half_rn(t[tx][ty + i]);
    }
}

// ---------------------------------------------------------------------------
// Mainloop compute: chunk = 64 K-columns as two 32-col sub-blocks.
// Stage layout: A sub0 +0, A sub1 +8192, B sub0 +16384, B sub1 +24576.
// Each sub-block: 128 rows x 64 B, 16B-chunk swizzle p = ch ^ ((r>>1)&3).
// ---------------------------------------------------------------------------

struct Frags {
    float acc[2][8][4];
};

__device__ __forceinline__ void compute_chunk(uint32_t base, int st, int lane,
                                              int wm, int wn, Frags& F)
{
    const uint32_t Ab = base + st;
    const uint32_t Bb = base + st + 16384;
    const int m8 = lane >> 3, l7 = lane & 7;
    #pragma unroll
    for (int ks = 0; ks < 4; ks++) {
        const uint32_t Asub = Ab + (ks >> 1) * 8192;
        const uint32_t Bsub = Bb + (ks >> 1) * 8192;
        const int kk = ks & 1;
        uint32_t a[2][4];
        #pragma unroll
        for (int mi = 0; mi < 2; mi++) {
            int rr = wm * 32 + mi * 16 + (m8 & 1) * 8 + l7;
            int ch = kk * 2 + (m8 >> 1);
            int p = ch ^ ((rr >> 1) & 3);
            ldsm4(a[mi], Asub + (uint32_t)(rr * 64 + p * 16));
        }
        #pragma unroll
        for (int jp = 0; jp < 4; jp++) {
            int nrow = wn * 64 + jp * 16 + (m8 >> 1) * 8 + l7;
            int ch = kk * 2 + (m8 & 1);
            int p = ch ^ ((nrow >> 1) & 3);
            uint32_t tb[4];
            ldsm4(tb, Bsub + (uint32_t)(nrow * 64 + p * 16));
            #pragma unroll
            for (int mi = 0; mi < 2; mi++) {
                mma_f16(F.acc[mi][2 * jp],     a[mi], tb[0], tb[1]);
                mma_f16(F.acc[mi][2 * jp + 1], a[mi], tb[2], tb[3]);
            }
        }
    }
}

// ---------------------------------------------------------------------------
// GEMM1: H = gelu(X @ W1 + b1).  A = Xh [32768][768], B = W1t [3072][768]
// Grid (24, 256), 256 threads, 2 CTAs/SM.  NC = 768/64 = 12.
// ---------------------------------------------------------------------------
__global__ void __launch_bounds__(256, 2)
k_mm1(const float* __restrict__ b1)
{
    extern __shared__ char smem[];
    const uint32_t base = smem_u32(smem);
    const int tid = threadIdx.x, wid = tid >> 5, lane = tid & 31;
    const int bx = blockIdx.x, by = blockIdx.y;
    const int K = 768, NC = 12;
    const int wm = wid & 3, wn = wid >> 2;

    auto issue = [&](int c) {
        int st = (c % NSTAGES) * STAGE_BYTES;
        #pragma unroll
        for (int t = 0; t < 8; t++) {
            int idx = tid + t * 256;           // 0..2047
            int region = idx >> 9;             // 0: A0, 1: A1, 2: B0, 3: B1
            int w = idx & 511, r = w >> 2, ch = w & 3;
            int sub = region & 1;
            int isB = region >> 1;
            int p = ch ^ ((r >> 1) & 3);
            uint32_t sa = base + st + isB * 16384 + sub * 8192 + r * 64 + p * 16;
            const __half* src;
            size_t grow;
            if (!isB) { src = g_Xh;  grow = (size_t)(by * 128 + r) * K; }
            else      { src = g_W1t; grow = (size_t)(bx * 128 + r) * K; }
            cp16(sa, src + grow + c * 64 + sub * 32 + ch * 8);
        }
        CP_COMMIT();
    };

    Frags F;
    #pragma unroll
    for (int mi = 0; mi < 2; mi++)
        #pragma unroll
        for (int nj = 0; nj < 8; nj++)
            #pragma unroll
            for (int q = 0; q < 4; q++) F.acc[mi][nj][q] = 0.0f;

    issue(0); issue(1);
    for (int c = 0; c < NC; c++) {
        CP_WAIT(1);
        __syncthreads();
        if (c + 2 < NC) issue(c + 2); else CP_COMMIT();
        compute_chunk(base, (c % NSTAGES) * STAGE_BYTES, lane, wm, wn, F);
    }

    // epilogue: bias + fast GELU -> fp16 into H
    const int g = lane >> 2, t4 = lane & 3;
    #pragma unroll
    for (int mi = 0; mi < 2; mi++) {
        #pragma unroll
        for (int nj = 0; nj < 8; nj++) {
            int row0 = by * 128 + wm * 32 + mi * 16 + g;
            int col  = bx * 128 + wn * 64 + nj * 8 + 2 * t4;
            float2 bb = *(const float2*)(b1 + col);
            float x0 = gelu_fast(F.acc[mi][nj][0] + bb.x);
            float x1 = gelu_fast(F.acc[mi][nj][1] + bb.y);
            float x2 = gelu_fast(F.acc[mi][nj][2] + bb.x);
            float x3 = gelu_fast(F.acc[mi][nj][3] + bb.y);
            __half2 h01 = __floats2half2_rn(x0, x1);
            __half2 h23 = __floats2half2_rn(x2, x3);
            *(uint32_t*)(g_Hf + (size_t)row0 * 3072 + col) =
                *reinterpret_cast<uint32_t*>(&h01);
            *(uint32_t*)(g_Hf + (size_t)(row0 + 8) * 3072 + col) =
                *reinterpret_cast<uint32_t*>(&h23);
        }
    }
}

// ---------------------------------------------------------------------------
// GEMM2: out = H @ [W2 | We[idx]] + [b2 | be[idx]].  Grid (6, 256), 2 CTAs/SM.
// NC = 3072/64 = 48. B rows n<576 from W2t, n>=576 from Wet[e]; 128-row M
// tiles never straddle a batch (1024 rows / batch).
// ---------------------------------------------------------------------------
__global__ void __launch_bounds__(256, 2)
k_mm2(const float* __restrict__ b2, const float* __restrict__ be,
      const int* __restrict__ idx32, float* __restrict__ out)
{
    extern __shared__ char smem[];
    const uint32_t base = smem_u32(smem);
    const int tid = threadIdx.x, wid = tid >> 5, lane = tid & 31;
    const int bx = blockIdx.x, by = blockIdx.y;
    const int K = 3072, NC = 48;
    const int wm = wid & 3, wn = wid >> 2;
    const int e = load_expert_index(idx32, by >> 3);

    auto issue = [&](int c) {
        int st = (c % NSTAGES) * STAGE_BYTES;
        #pragma unroll
        for (int t = 0; t < 8; t++) {
            int idx = tid + t * 256;
            int region = idx >> 9;
            int w = idx & 511, r = w >> 2, ch = w & 3;
            int sub = region & 1;
            int isB = region >> 1;
            int p = ch ^ ((r >> 1) & 3);
            uint32_t sa = base + st + isB * 16384 + sub * 8192 + r * 64 + p * 16;
            const __half* src;
            size_t grow;
            if (!isB) {
                src = g_Hf;
                grow = (size_t)(by * 128 + r) * K;
            } else {
                int n = bx * 128 + r;
                if (n < 576) { src = g_W2t; grow = (size_t)n * K; }
                else { src = g_Wet; grow = ((size_t)e * 192 + (n - 576)) * K; }
            }
            cp16(sa, src + grow + c * 64 + sub * 32 + ch * 8);
        }
        CP_COMMIT();
    };

    Frags F;
    #pragma unroll
    for (int mi = 0; mi < 2; mi++)
        #pragma unroll
        for (int nj = 0; nj < 8; nj++)
            #pragma unroll
            for (int q = 0; q < 4; q++) F.acc[mi][nj][q] = 0.0f;

    issue(0); issue(1);
    for (int c = 0; c < NC; c++) {
        CP_WAIT(1);
        __syncthreads();
        if (c + 2 < NC) issue(c + 2); else CP_COMMIT();
        compute_chunk(base, (c % NSTAGES) * STAGE_BYTES, lane, wm, wn, F);
    }

    // epilogue: + bias (shared / expert), fp32 out [32768][768]
    const int g = lane >> 2, t4 = lane & 3;
    #pragma unroll
    for (int mi = 0; mi < 2; mi++) {
        #pragma unroll
        for (int nj = 0; nj < 8; nj++) {
            int row0 = by * 128 + wm * 32 + mi * 16 + g;
            int col  = bx * 128 + wn * 64 + nj * 8 + 2 * t4;
            float bx0, bx1;
            if (col < 576) { float2 bb = *(const float2*)(b2 + col); bx0 = bb.x; bx1 = bb.y; }
            else { float2 bb = *(const float2*)(be + e * 192 + (col - 576)); bx0 = bb.x; bx1 = bb.y; }
            float2 v0 = make_float2(F.acc[mi][nj][0] + bx0, F.acc[mi][nj][1] + bx1);
            float2 v1 = make_float2(F.acc[mi][nj][2] + bx0, F.acc[mi][nj][3] + bx1);
            *(float2*)(out + (size_t)row0 * 768 + col) = v0;
            *(float2*)(out + (size_t)(row0 + 8) * 768 + col) = v1;
        }
    }
}

// ---------------------------------------------------------------------------
extern "C" void kernel_launch(void* const* d_in, const int* in_sizes, int n_in,
                              void* d_out, int out_size)
{
    (void)in_sizes; (void)n_in; (void)out_size;
    const float* X   = (const float*)d_in[0];
    const int*   idx = (const int*)d_in[1];
    const float* W1  = (const float*)d_in[2];
    const float* b1  = (const float*)d_in[3];
    const float* W2  = (const float*)d_in[4];
    const float* b2  = (const float*)d_in[5];
    const float* We  = (const float*)d_in[6];
    const float* be  = (const float*)d_in[7];
    float* out = (float*)d_out;

    cudaFuncSetAttribute(k_mm1, cudaFuncAttributeMaxDynamicSharedMemorySize, SMEM_TOTAL);
    cudaFuncSetAttribute(k_mm2, cudaFuncAttributeMaxDynamicSharedMemorySize, SMEM_TOTAL);

    __half *xh, *w1t, *w2t, *wet;
    cudaGetSymbolAddress((void**)&xh,  g_Xh);
    cudaGetSymbolAddress((void**)&w1t, g_W1t);
    cudaGetSymbolAddress((void**)&w2t, g_W2t);
    cudaGetSymbolAddress((void**)&wet, g_Wet);

    {
        size_t n = (size_t)32768 * 768;
        k_half<<<(unsigned)(n / (256 * 4)), 256>>>(X, xh, n);
    }
    {
        dim3 b(32, 8);
        k_thalf<<<dim3(3072 / 32, 768 / 32, 1), b>>>(W1, w1t, 768, 3072);
        k_thalf<<<dim3(576 / 32, 3072 / 32, 1), b>>>(W2, w2t, 3072, 576);
        k_thalf<<<dim3(192 / 32, 3072 / 32, 6), b>>>(We, wet, 3072, 192);
    }

    k_mm1<<<dim3(3072 / 128, 32768 / 128), 256, SMEM_TOTAL>>>(b1);
    k_mm2<<<dim3(768 / 128, 32768 / 128), 256, SMEM_TOTAL>>>(b2, be, idx, out);
}